// round 6
// baseline (speedup 1.0000x reference)
#include <cuda_runtime.h>

#define TPB 256
#define NBLK 888                      // 6 CTAs/SM * 148 SMs, co-resident
#define BITEMS 8
#define BTILE 2048                    // TPB * BITEMS
#define AITEMS 4
#define ATILE 1024                    // TPB * AITEMS
#define MAX_BOND (1 << 22)
#define MAX_ATOM (1 << 20)
#define MAX_BTILES (MAX_BOND / BTILE)
#define MAX_ATILES (MAX_ATOM / ATILE)
#define MAX_GROUPS (1 << 22)          // up to 33.5M triples
#define CUTOFF 0.8f

// ---------------- scratch (static device globals; no allocations) ----------
__device__ int g_deg[MAX_ATOM];
__device__ int2 g_ab[MAX_ATOM];       // {bondOff, deg}
__device__ int g_triStart[MAX_ATOM];
__device__ float g_keptF[MAX_BOND];   // kept bond ids, pre-converted to float
__device__ unsigned long long g_mask[MAX_BOND / 64];
__device__ int g_tileCnt[MAX_BTILES];
__device__ int g_tileOff[MAX_BTILES];
__device__ unsigned long long g_atPack[MAX_ATILES];
__device__ unsigned long long g_atPackOff[MAX_ATILES];
__device__ int2 g_grp[MAX_GROUPS];    // per-8-triple group: {off, d<<20|j<<10|kp}
__device__ int g_T;
__device__ int g_bound[260];
__device__ volatile int g_barArrive;
__device__ volatile unsigned g_barGen;

// ---------------- helpers ---------------------------------------------------
__device__ __forceinline__ void gridBarrier() {
    __syncthreads();
    if (threadIdx.x == 0) {
        __threadfence();
        unsigned gen = g_barGen;
        if (atomicAdd((int*)&g_barArrive, 1) == NBLK - 1) {
            g_barArrive = 0;
            __threadfence();
            g_barGen = gen + 1;
        } else {
            while (g_barGen == gen) __nanosleep(64);
        }
        __threadfence();
    }
    __syncthreads();
}

template <typename T>
__device__ __forceinline__ T warpIncl(T v) {
#pragma unroll
    for (int d = 1; d < 32; d <<= 1) {
        T n = __shfl_up_sync(0xffffffffu, v, d);
        if ((threadIdx.x & 31) >= d) v += n;
    }
    return v;
}

template <typename T>
__device__ __forceinline__ T blockExcl(T v, T* smem, T* total) {
    int lane = threadIdx.x & 31, w = threadIdx.x >> 5, nw = TPB >> 5;
    T inc = warpIncl(v);
    if (lane == 31) smem[w] = inc;
    __syncthreads();
    if (w == 0) {
        T x = (lane < nw) ? smem[lane] : (T)0;
        T xi = warpIncl(x);
        if (lane < nw) smem[lane] = xi - x;
        if (lane == nw - 1) smem[32] = xi;
    }
    __syncthreads();
    T res = inc - v + smem[w];
    T tot = smem[32];
    __syncthreads();
    if (total) *total = tot;
    return res;
}

// ---------------- the fused kernel ------------------------------------------
__global__ __launch_bounds__(TPB, 6) void fused(
    const int* __restrict__ src, const float* __restrict__ len,
    const int* __restrict__ n_atoms, int n_bond, int n_struct,
    float* __restrict__ out, int out_size) {
    __shared__ unsigned long long smLL[33];
    __shared__ int smStage[BTILE];

    int tid = threadIdx.x;
    int gtid = blockIdx.x * TPB + tid;
    const int gsize = NBLK * TPB;
    int nTiles = (n_bond + BTILE - 1) / BTILE;

    // nA computed by every thread (tiny loop, broadcast loads)
    int nA = 0;
    for (int s = 0; s < n_struct; s++) nA += n_atoms[s];

    // ---- P0: zero degrees; struct bounds ----
    for (int i = gtid; i < nA; i += gsize) g_deg[i] = 0;
    if (gtid == 0) {
        int ns = n_struct < 256 ? n_struct : 256;
        int acc = 0;
        for (int s = 0; s < ns; s++) { g_bound[s] = acc; acc += n_atoms[s]; }
        g_bound[ns] = acc;
    }
    gridBarrier();

    // ---- P1: filter (mask + per-tile counts + run-aggregated degrees) ----
    for (int tile = blockIdx.x; tile < nTiles; tile += NBLK) {
        int base = tile * BTILE + tid * BITEMS;
        unsigned bf = 0;
        int curA = -1, curC = 0;
        if (base + BITEMS <= n_bond) {
            float4 l0 = *(const float4*)(len + base);
            float4 l1 = *(const float4*)(len + base + 4);
            int4 s0 = *(const int4*)(src + base);
            int4 s1 = *(const int4*)(src + base + 4);
            float lv[8] = {l0.x, l0.y, l0.z, l0.w, l1.x, l1.y, l1.z, l1.w};
            int sv[8] = {s0.x, s0.y, s0.z, s0.w, s1.x, s1.y, s1.z, s1.w};
#pragma unroll
            for (int i = 0; i < 8; i++) {
                if (lv[i] <= CUTOFF) {
                    bf |= 1u << i;
                    if (sv[i] == curA) curC++;
                    else { if (curC) atomicAdd(&g_deg[curA], curC); curA = sv[i]; curC = 1; }
                }
            }
        } else {
            for (int i = 0; i < BITEMS; i++) {
                int b = base + i;
                if (b < n_bond && len[b] <= CUTOFF) {
                    bf |= 1u << i;
                    int a = src[b];
                    if (a == curA) curC++;
                    else { if (curC) atomicAdd(&g_deg[curA], curC); curA = a; curC = 1; }
                }
            }
        }
        if (curC) atomicAdd(&g_deg[curA], curC);
        unsigned long long word = (unsigned long long)bf << ((tid & 7) * 8);
        word |= __shfl_xor_sync(0xffffffffu, word, 1);
        word |= __shfl_xor_sync(0xffffffffu, word, 2);
        word |= __shfl_xor_sync(0xffffffffu, word, 4);
        if ((tid & 7) == 0) g_mask[tile * 32 + (tid >> 3)] = word;
        int tot;
        blockExcl<int>(__popc(bf), (int*)smLL, &tot);
        if (tid == 0) g_tileCnt[tile] = tot;
    }
    gridBarrier();

    // ---- P2: block 0 scans bond-tile counts ----
    if (blockIdx.x == 0) {
        int carry = 0;
        for (int b0 = 0; b0 < nTiles; b0 += TPB) {
            int i = b0 + tid;
            int v = (i < nTiles) ? g_tileCnt[i] : 0;
            int tot;
            int e = blockExcl<int>(v, (int*)smLL, &tot);
            if (i < nTiles) g_tileOff[i] = carry + e;
            carry += tot;
        }
    }
    gridBarrier();

    int nAT = (nA + ATILE - 1) / ATILE;

    // ---- P3a: scatter kept bond ids as floats (smem-staged, coalesced) ----
    for (int tile = blockIdx.x; tile < nTiles; tile += NBLK) {
        int base = tile * BTILE + tid * BITEMS;
        unsigned bf = 0;
        if (base < n_bond) {
            unsigned long long w = g_mask[tile * 32 + (tid >> 3)];
            bf = (unsigned)(w >> ((tid & 7) * 8)) & 0xFFu;
        }
        int tot;
        int e = blockExcl<int>(__popc(bf), (int*)smLL, &tot);
#pragma unroll
        for (int i = 0; i < 8; i++)
            if ((bf >> i) & 1u) smStage[e++] = base + i;
        __syncthreads();
        int off = g_tileOff[tile];
        for (int i = tid; i < tot; i += TPB) g_keptF[off + i] = (float)smStage[i];
        __syncthreads();
    }

    // ---- P3b: n_triple_ij section ----
    int offTij = out_size - n_struct - nA - n_bond;
    int nBG = (n_bond + 3) >> 2;
    for (int q = gtid; q < nBG; q += gsize) {
        int b0 = q * 4;
        unsigned long long w = g_mask[b0 >> 6];
        unsigned nib = (unsigned)(w >> (b0 & 63)) & 0xFu;
        if (b0 + 4 <= n_bond) {
            int4 s = *(const int4*)(src + b0);
            float4 r;
            r.x = (nib & 1u) ? (float)(g_deg[s.x] - 1) : 0.0f;
            r.y = (nib & 2u) ? (float)(g_deg[s.y] - 1) : 0.0f;
            r.z = (nib & 4u) ? (float)(g_deg[s.z] - 1) : 0.0f;
            r.w = (nib & 8u) ? (float)(g_deg[s.w] - 1) : 0.0f;
            __stcs((float4*)(out + offTij + b0), r);  // 2T even, b0%4==0 -> aligned
        } else {
            for (int i = 0; b0 + i < n_bond; i++)
                out[offTij + b0 + i] =
                    ((nib >> i) & 1u) ? (float)(g_deg[src[b0 + i]] - 1) : 0.0f;
        }
    }

    // ---- P3c: per-atom-tile packed (tri<<32 | deg) sums ----
    for (int t = blockIdx.x; t < nAT; t += NBLK) {
        int base = t * ATILE + tid * AITEMS;
        unsigned long long acc = 0;
#pragma unroll
        for (int i = 0; i < 4; i++) {
            int a = base + i;
            int d = (a < nA) ? g_deg[a] : 0;
            acc += ((unsigned long long)(unsigned)(d * (d - 1)) << 32) | (unsigned)d;
        }
        unsigned long long tot;
        blockExcl<unsigned long long>(acc, smLL, &tot);
        if (tid == 0) g_atPack[t] = tot;
    }
    gridBarrier();

    // ---- P4: block 0 scans atom-tile sums ----
    if (blockIdx.x == 0) {
        unsigned long long carry = 0;
        for (int b0 = 0; b0 < nAT; b0 += TPB) {
            int i = b0 + tid;
            unsigned long long v = (i < nAT) ? g_atPack[i] : 0ull;
            unsigned long long tot;
            unsigned long long e = blockExcl<unsigned long long>(v, smLL, &tot);
            if (i < nAT) g_atPackOff[i] = carry + e;
            carry += tot;
        }
        if (tid == 0) g_T = (int)(carry >> 32);
    }
    gridBarrier();

    // ---- P5: per-atom CSR offsets, triStart, n_triple_i section ----
    int offTi = out_size - n_struct - nA;
    for (int t = blockIdx.x; t < nAT; t += NBLK) {
        int base = t * ATILE + tid * AITEMS;
        int dA[4];
        unsigned long long acc = 0;
#pragma unroll
        for (int i = 0; i < 4; i++) {
            int a = base + i;
            int d = (a < nA) ? g_deg[a] : 0;
            dA[i] = d;
            acc += ((unsigned long long)(unsigned)(d * (d - 1)) << 32) | (unsigned)d;
        }
        unsigned long long e =
            blockExcl<unsigned long long>(acc, smLL, (unsigned long long*)0);
        unsigned long long run = g_atPackOff[t] + e;
#pragma unroll
        for (int i = 0; i < 4; i++) {
            int a = base + i;
            if (a < nA) {
                int d = dA[i];
                g_ab[a] = make_int2((int)(run & 0xffffffffull), d);
                g_triStart[a] = (int)(run >> 32);
                out[offTi + a] = (float)(d * (d - 1));
                run += ((unsigned long long)(unsigned)(d * (d - 1)) << 32) | (unsigned)d;
            }
        }
    }
    gridBarrier();

    // ---- P6: group record fill (full grid), precomputed (j,kp) ----
    for (int a = gtid; a < nA; a += gsize) {
        int2 ab = g_ab[a];
        int d = ab.y;
        if (d < 2) continue;
        int ts = g_triStart[a];
        int dm1 = d - 1;
        int tri = d * dm1;
        int g0 = (ts + 7) >> 3, g1 = (ts + tri + 7) >> 3;
        int local = (g0 << 3) - ts;
        int j = local / dm1;
        int kp = local - j * dm1;
        int dbits = d << 20;
        for (int g = g0; g < g1; g++) {
            __stcs(&g_grp[g], make_int2(ab.x, dbits | (j << 10) | kp));
            kp += 8;
            while (kp >= dm1) { kp -= dm1; j++; }
        }
    }
    gridBarrier();

    // ---- P7: struct sums + pair emission ----
    int T = g_T;
    if (gtid < n_struct) {
        int lo = g_bound[gtid], hi = g_bound[gtid + 1];
        int vlo = (lo >= nA) ? T : g_triStart[lo];
        int vhi = (hi >= nA) ? T : g_triStart[hi];
        out[out_size - n_struct + gtid] = (float)(vhi - vlo);
    }
    int nG = (T + 7) >> 3;
    for (int g = gtid; g < nG; g += gsize) {
        int t0 = g << 3;
        int2 rec = __ldcs(&g_grp[g]);
        int off = rec.x;
        int kp = rec.y & 1023;
        int j = (rec.y >> 10) & 1023;
        int d = ((unsigned)rec.y) >> 20;
        int dm1 = d - 1;
        int n = min(8, T - t0);
        float vals[16];
#pragma unroll
        for (int i = 0; i < 8; i++) {
            if (i < n) {
                vals[2 * i] = __ldg(&g_keptF[off + j]);
                vals[2 * i + 1] = __ldg(&g_keptF[off + kp + (kp >= j)]);
                if (i + 1 < n) {
                    if (++kp == dm1) {
                        kp = 0;
                        if (++j == d) {
                            // crossing: binary search atom owning triple t0+i+1
                            int t = t0 + i + 1;
                            int lo = 0, hi = nA - 1;
                            while (lo < hi) {
                                int mid = (lo + hi + 1) >> 1;
                                if (g_triStart[mid] <= t) lo = mid; else hi = mid - 1;
                            }
                            int2 ab = g_ab[lo];
                            off = ab.x; d = ab.y; dm1 = d - 1; j = 0; kp = 0;
                        }
                    }
                }
            }
        }
        if (n == 8) {
            float4* o4 = (float4*)(out + 2 * t0);  // 64B aligned
            __stcs(o4 + 0, make_float4(vals[0], vals[1], vals[2], vals[3]));
            __stcs(o4 + 1, make_float4(vals[4], vals[5], vals[6], vals[7]));
            __stcs(o4 + 2, make_float4(vals[8], vals[9], vals[10], vals[11]));
            __stcs(o4 + 3, make_float4(vals[12], vals[13], vals[14], vals[15]));
        } else {
            for (int i = 0; i < n; i++) {
                out[2 * (t0 + i)] = vals[2 * i];
                out[2 * (t0 + i) + 1] = vals[2 * i + 1];
            }
        }
    }
}

// ---------------- launch ----------------------------------------------------
extern "C" void kernel_launch(void* const* d_in, const int* in_sizes, int n_in,
                              void* d_out, int out_size) {
    const int* src = (const int*)d_in[0];
    const float* len = (const float*)d_in[1];
    const int* n_atoms = (const int*)d_in[2];
    int n_bond = in_sizes[0];
    int n_struct = in_sizes[2];
    fused<<<NBLK, TPB>>>(src, len, n_atoms, n_bond, n_struct, (float*)d_out,
                         out_size);
}